// round 15
// baseline (speedup 1.0000x reference)
#include <cuda_runtime.h>
#include <cuda_bf16.h>
#include <cuda_fp8.h>
#include <math.h>
#include <stdint.h>

#define DEV __device__ __forceinline__

constexpr int Bn   = 256;
constexpr int Rimg = 36;
constexpr int Lcap = 32;
constexpr int Dm   = 1024;
constexpr int ROWS_IMG = Bn * Rimg;   // 9216
constexpr int ROWS_CAP = Bn * Lcap;   // 8192
constexpr int TOPC = 16;              // candidates kept for exact rescoring

// ---- GEMM tiling: CTA 256x128, 512 threads, fp8 K-major, 64B stage rows ----
constexpr int TM = 256;
constexpr int TN = 128;
constexpr int KSB  = 64;                       // bytes (=64 fp8 elems) per stage row
constexpr int NSTG = Dm / KSB;                 // 16 stages
constexpr int A_PL = TM * KSB;                 // 16384 B
constexpr int B_PL = TN * KSB;                 // 8192 B
constexpr int STG  = A_PL + B_PL;              // 24576 B per stage
constexpr int DYN_SMEM = 3 * STG + 1024;       // 74752

// ---------------- device scratch (no allocations allowed) ----------------
__device__ float g_imgN[ROWS_IMG * Dm];
__device__ float g_capN[ROWS_CAP * Dm];
__device__ float g_imgP[ROWS_IMG * Dm];
__device__ float g_capP[ROWS_CAP * Dm];
__device__ uint8_t g_imgN_f8[ROWS_IMG * Dm];
__device__ uint8_t g_capN_f8[ROWS_CAP * Dm];
__device__ uint8_t g_imgP_f8[ROWS_IMG * Dm];
__device__ uint8_t g_capP_f8[ROWS_CAP * Dm];
__device__ float g_pcmax1[2 * Bn * ROWS_IMG];  // call-1 [slot][n][col]
__device__ float g_pcmax2[2 * Bn * ROWS_CAP];  // call-2 (streams overlap)
__device__ int   g_ti8a[Bn * TOPC];
__device__ int   g_ti8b[Bn * TOPC];
__device__ float g_sc8a[Bn * TOPC];
__device__ float g_sc8b[Bn * TOPC];
__device__ float g_tv1[Bn * 3];
__device__ int   g_ti1[Bn * 3];
__device__ float g_tv2[Bn * 3];
__device__ int   g_ti2[Bn * 3];
__device__ float g_m2k1[Bn * 3];
__device__ float g_m2k2[Bn * 3];

// ---- stream/event infra (host-side statics, created before any capture) --
namespace {
struct StreamInit {
    cudaStream_t s1;
    cudaEvent_t e0, e2;
    StreamInit() {
        cudaStreamCreateWithFlags(&s1, cudaStreamNonBlocking);
        cudaEventCreateWithFlags(&e0, cudaEventDisableTiming);
        cudaEventCreateWithFlags(&e2, cudaEventDisableTiming);
    }
};
StreamInit g_si;
}

// ---------------- PTX helpers ----------------
DEV unsigned smem_u32(const void* p) {
    unsigned a;
    asm("{ .reg .u64 t; cvta.to.shared.u64 t, %1; cvt.u32.u64 %0, t; }" : "=r"(a) : "l"(p));
    return a;
}
DEV void cp16u(unsigned smem_dst, const void* gmem_src) {
    asm volatile("cp.async.cg.shared.global [%0], [%1], 16;" :: "r"(smem_dst), "l"(gmem_src));
}
#define CP_COMMIT() asm volatile("cp.async.commit_group;")
#define CP_WAIT(n)  asm volatile("cp.async.wait_group %0;" :: "n"(n) : "memory")

DEV void ldsm4(unsigned* d, unsigned addr) {
    asm volatile("ldmatrix.sync.aligned.m8n8.x4.shared.b16 {%0,%1,%2,%3}, [%4];"
                 : "=r"(d[0]), "=r"(d[1]), "=r"(d[2]), "=r"(d[3]) : "r"(addr));
}
// fp8 e4m3 MMA m16n8k32: fragment layout == bf16 m16n8k16 with elem = fp8 pair
DEV void mma_fp8(float* c, const unsigned* a, unsigned b0, unsigned b1) {
    asm volatile(
        "mma.sync.aligned.m16n8k32.row.col.f32.e4m3.e4m3.f32 "
        "{%0,%1,%2,%3},{%4,%5,%6,%7},{%8,%9},{%0,%1,%2,%3};"
        : "+f"(c[0]), "+f"(c[1]), "+f"(c[2]), "+f"(c[3])
        : "r"(a[0]), "r"(a[1]), "r"(a[2]), "r"(a[3]), "r"(b0), "r"(b1));
}

// ---- fused L2-normalize of all four tensors; emit fp32 + e4m3 (x16) -------
__global__ void norm4_kernel(const float* __restrict__ i0, const float* __restrict__ i1,
                             const float* __restrict__ i2, const float* __restrict__ i3,
                             float* __restrict__ o0, float* __restrict__ o1,
                             float* __restrict__ o2, float* __restrict__ o3,
                             uint8_t* __restrict__ h0, uint8_t* __restrict__ h1,
                             uint8_t* __restrict__ h2, uint8_t* __restrict__ h3) {
    int gw = (blockIdx.x * blockDim.x + threadIdx.x) >> 5;
    int lane = threadIdx.x & 31;
    const float* in; float* out; uint8_t* oh; int row;
    if (gw < ROWS_IMG)                    { in = i0; out = o0; oh = h0; row = gw; }
    else if (gw < ROWS_IMG + ROWS_CAP)    { in = i1; out = o1; oh = h1; row = gw - ROWS_IMG; }
    else if (gw < 2 * ROWS_IMG + ROWS_CAP){ in = i2; out = o2; oh = h2; row = gw - ROWS_IMG - ROWS_CAP; }
    else if (gw < 2 * ROWS_IMG + 2 * ROWS_CAP)
                                          { in = i3; out = o3; oh = h3; row = gw - 2 * ROWS_IMG - ROWS_CAP; }
    else return;

    const float4* src = reinterpret_cast<const float4*>(in + (size_t)row * Dm);
    float4* dst       = reinterpret_cast<float4*>(out + (size_t)row * Dm);
    uint8_t* dh = oh + (size_t)row * Dm;
    float4 v[8];
    float ss = 0.f;
#pragma unroll
    for (int i = 0; i < 8; i++) {
        v[i] = src[lane + 32 * i];
        ss += v[i].x * v[i].x + v[i].y * v[i].y + v[i].z * v[i].z + v[i].w * v[i].w;
    }
#pragma unroll
    for (int o = 16; o > 0; o >>= 1) ss += __shfl_xor_sync(0xffffffffu, ss, o);
    float inv = 1.0f / fmaxf(sqrtf(ss), 1e-8f);
#pragma unroll
    for (int i = 0; i < 8; i++) {
        float4 w = v[i];
        w.x *= inv; w.y *= inv; w.z *= inv; w.w *= inv;
        dst[lane + 32 * i] = w;
        // fp8 plane, pre-scaled x16 (avoids e4m3 denormals; scale cancels in ranking)
        __nv_fp8_e4m3 f0(w.x * 16.f), f1(w.y * 16.f), f2(w.z * 16.f), f3(w.w * 16.f);
        unsigned pk = (unsigned)f0.__x | ((unsigned)f1.__x << 8)
                    | ((unsigned)f2.__x << 16) | ((unsigned)f3.__x << 24);
        *reinterpret_cast<unsigned*>(dh + (lane + 32 * i) * 4) = pk;
    }
}

// ------- phase-1: 1-pass fp8 GEMM + group colmax (addressing == bf16 ver) --
template <int R>
__global__ __launch_bounds__(512, 1)
void gemm_colmax(const uint8_t* __restrict__ Af8,
                 const uint8_t* __restrict__ Bf8,
                 float* __restrict__ pcmax, int CT) {
    extern __shared__ char dynsm[];
    const int tid  = threadIdx.x;
    const int lane = tid & 31;
    const int wid  = tid >> 5;
    const int wm   = wid >> 2;        // 0..3 -> rows wm*64
    const int wn   = wid & 3;         // 0..3 -> cols wn*32

    const unsigned smb0 = smem_u32(dynsm);
    const unsigned smb  = (smb0 + 1023u) & ~1023u;
    char* smp = dynsm + (smb - smb0);

    const uint8_t* Ah = Af8 + (size_t)blockIdx.y * TM * Dm;
    const uint8_t* Bh = Bf8 + (size_t)blockIdx.x * TN * Dm;

    float c[4][4][4];
#pragma unroll
    for (int mf = 0; mf < 4; mf++)
#pragma unroll
        for (int nf = 0; nf < 4; nf++)
#pragma unroll
            for (int r = 0; r < 4; r++) c[mf][nf][r] = 0.f;

    // ldmatrix lane address components (kk=0; kk=1 => XOR 32 bytes)
    const int rAl = lane & 15, hiA = lane >> 4;
    const unsigned offA = (unsigned)((wm * 64 + rAl) * 64 + ((hiA ^ ((rAl >> 1) & 3)) * 16));
    const int nB = ((lane >> 4) & 1) * 8 + (lane & 7), hiB = (lane >> 3) & 1;
    const unsigned offB = (unsigned)((wn * 32 + nB) * 64 + ((hiB ^ ((nB >> 1) & 3)) * 16));

    auto load_stage = [&](int s) {
        const unsigned sb = smb + (unsigned)(s % 3) * STG;
        const int k0 = s * KSB;                   // byte offset in row
#pragma unroll
        for (int i = 0; i < 3; i++) {
            int idx = tid + i * 512;              // 0..1535
            if (idx < 1024) {                     // A: 256 rows x 4 x 16B chunks
                int r = idx >> 2, ch = idx & 3;
                cp16u(sb + r * 64 + ((ch ^ ((r >> 1) & 3)) * 16),
                      Ah + (size_t)r * Dm + k0 + ch * 16);
            } else {                              // B: 128 rows x 4 x 16B chunks
                int t2 = idx - 1024;
                int r = t2 >> 2, ch = t2 & 3;
                cp16u(sb + A_PL + r * 64 + ((ch ^ ((r >> 1) & 3)) * 16),
                      Bh + (size_t)r * Dm + k0 + ch * 16);
            }
        }
        CP_COMMIT();
    };

    load_stage(0);
    load_stage(1);

#pragma unroll 1
    for (int s = 0; s < NSTG; s++) {
        if (s < NSTG - 1) { CP_WAIT(1); } else { CP_WAIT(0); }
        __syncthreads();

        const unsigned sb  = smb + (unsigned)(s % 3) * STG;
        const unsigned aAh = sb + offA;
        const unsigned aBh = sb + A_PL + offB;

#pragma unroll
        for (int kk = 0; kk < 2; kk++) {          // two k32 halves per 64B row
            const unsigned kx = kk * 32;
            unsigned bh[2][4], af[4][4];
#pragma unroll
            for (int j = 0; j < 2; j++) ldsm4(bh[j], (aBh + j * 1024) ^ kx);
#pragma unroll
            for (int mf = 0; mf < 4; mf++) ldsm4(af[mf], (aAh + mf * 1024) ^ kx);
#pragma unroll
            for (int mf = 0; mf < 4; mf++)
#pragma unroll
                for (int j = 0; j < 2; j++)
#pragma unroll
                    for (int sub = 0; sub < 2; sub++) {
                        int nf = j * 2 + sub;
                        mma_fp8(c[mf][nf], af[mf], bh[j][sub * 2], bh[j][sub * 2 + 1]);
                    }
        }
        if (s + 2 < NSTG) load_stage(s + 2);
    }
    __syncthreads();

    // ---- epilogue: two 128-row halves through smem [128][132] -------------
    float* red = reinterpret_cast<float*>(smp);
    const int m0 = blockIdx.y * TM;
    const int col = tid;                   // only tid<128 scans
    const size_t colg = (size_t)blockIdx.x * TN + (col & 127);
    int   curg = m0 / R;
    float curv = -INFINITY;
    const int lr = lane >> 2;
    const int lc = (lane & 3) * 2;

#pragma unroll 1
    for (int h = 0; h < 2; h++) {
        if ((wm >> 1) == h) {
            const int r0 = (wm & 1) * 64;
#pragma unroll
            for (int mf = 0; mf < 4; mf++)
#pragma unroll
                for (int nf = 0; nf < 4; nf++) {
                    int rr = r0 + mf * 16 + lr;
                    int cc = wn * 32 + nf * 8 + lc;
                    *(float2*)&red[rr * 132 + cc]       = make_float2(c[mf][nf][0], c[mf][nf][1]);
                    *(float2*)&red[(rr + 8) * 132 + cc] = make_float2(c[mf][nf][2], c[mf][nf][3]);
                }
        }
        __syncthreads();
        if (tid < 128) {
#pragma unroll 1
            for (int r = 0; r < 128; r++) {
                int grp = (m0 + h * 128 + r) / R;
                float v = red[r * 132 + col];
                if (grp != curg) {
                    int slot = blockIdx.y - (curg * R) / TM;
                    pcmax[(size_t)slot * Bn * CT + (size_t)curg * CT + colg] = curv;
                    curg = grp;
                    curv = v;
                } else {
                    curv = fmaxf(curv, v);
                }
            }
        }
        __syncthreads();
    }
    if (tid < 128) {
        int slot = blockIdx.y - (curg * R) / TM;
        pcmax[(size_t)slot * Bn * CT + (size_t)curg * CT + colg] = curv;
    }
}

// ------- approximate sim row-sum + warp-select top-16 ----------------------
template <int L, int R>
__global__ void sim_topc_kernel(const float* __restrict__ pcmax, int CT,
                                int* __restrict__ tic) {
    const int n = blockIdx.x;
    const int t = threadIdx.x;  // 256 candidate p's
    const bool two = ((n * R) / TM) != ((n * R + R - 1) / TM);
    const float* b0 = pcmax + (size_t)n * CT + (size_t)t * L;
    const float* b1 = b0 + (size_t)Bn * CT;
    float s = 0.f;
#pragma unroll
    for (int l = 0; l < L; l++) {
        float v = b0[l];
        if (two) v = fmaxf(v, b1[l]);
        s += v;
    }
    __shared__ float sv[256];
    sv[t] = s;
    __syncthreads();
    if (t < 32) {
        for (int k = 0; k < TOPC; k++) {
            float bv = -INFINITY; int bi = 0x7fffffff;
#pragma unroll
            for (int j = 0; j < 8; j++) {
                int e = t + 32 * j;
                float v = sv[e];
                if (v > bv || (v == bv && e < bi)) { bv = v; bi = e; }
            }
#pragma unroll
            for (int o = 16; o > 0; o >>= 1) {
                float ov = __shfl_xor_sync(0xffffffffu, bv, o);
                int oi = __shfl_xor_sync(0xffffffffu, bi, o);
                if (ov > bv || (ov == bv && oi < bi)) { bv = ov; bi = oi; }
            }
            if (t == 0) { tic[n * TOPC + k] = bi; sv[bi] = -INFINITY; }
            __syncwarp();
        }
    }
}

// ---- exact fp32 score (R11 proven form): A-tile shared across all --------
// candidates of one n. thread = (cand, l); float4 smem broadcast + FMA.
template <int R2, int L2, int CAND>
__global__ __launch_bounds__(CAND * L2)
void score3_kernel(const float* __restrict__ A, const float* __restrict__ Bmat,
                   const int* __restrict__ ti, float* __restrict__ outv) {
    constexpr int KC = 32;
    constexpr int THREADS = CAND * L2;
    __shared__ __align__(16) float As[R2][KC + 4];
    __shared__ float cmax_sh[THREADS];

    const int n = blockIdx.x;
    const int tid = threadIdx.x;
    const int cand = tid / L2;
    const int l = tid % L2;
    const int p = ti[n * CAND + cand];

    const float* Ab = A + (size_t)n * R2 * Dm;
    const float* Bb = Bmat + ((size_t)p * L2 + l) * Dm;

    float acc[R2];
#pragma unroll
    for (int r = 0; r < R2; r++) acc[r] = 0.f;

#pragma unroll 1
    for (int c2 = 0; c2 < Dm / KC; c2++) {
        float4 b4[KC / 4];
#pragma unroll
        for (int q = 0; q < KC / 4; q++) b4[q] = *(const float4*)(Bb + c2 * KC + q * 4);
        __syncthreads();
        for (int idx = tid; idx < R2 * (KC / 4); idx += THREADS) {
            int r = idx / (KC / 4), q = idx % (KC / 4);
            *(float4*)&As[r][q * 4] = *(const float4*)(Ab + (size_t)r * Dm + c2 * KC + q * 4);
        }
        __syncthreads();
#pragma unroll
        for (int r = 0; r < R2; r++) {
#pragma unroll
            for (int q = 0; q < KC / 4; q++) {
                float4 a4 = *(const float4*)&As[r][q * 4];   // broadcast
                acc[r] = fmaf(a4.x, b4[q].x, acc[r]);
                acc[r] = fmaf(a4.y, b4[q].y, acc[r]);
                acc[r] = fmaf(a4.z, b4[q].z, acc[r]);
                acc[r] = fmaf(a4.w, b4[q].w, acc[r]);
            }
        }
    }

    float m = acc[0];
#pragma unroll
    for (int r = 1; r < R2; r++) m = fmaxf(m, acc[r]);
    cmax_sh[tid] = m;
    __syncthreads();
    if (tid < CAND) {
        float s = 0.f;
        for (int j = 0; j < L2; j++) s += cmax_sh[tid * L2 + j];
        outv[n * CAND + tid] = s;
    }
}

// ---- exact top-3 of the TOPC rescored candidates (low-idx tie-break) ------
__global__ void top3_ofc_kernel(const float* __restrict__ scc, const int* __restrict__ tic,
                                float* __restrict__ tv, int* __restrict__ ti) {
    const int n = blockIdx.x;
    if (threadIdx.x != 0) return;
    float v[TOPC]; int id[TOPC];
#pragma unroll
    for (int j = 0; j < TOPC; j++) { v[j] = scc[n * TOPC + j]; id[j] = tic[n * TOPC + j]; }
    for (int k = 0; k < 3; k++) {
        int best = k;
        for (int j = k + 1; j < TOPC; j++)
            if (v[j] > v[best] || (v[j] == v[best] && id[j] < id[best])) best = j;
        float tvv = v[k]; v[k] = v[best]; v[best] = tvv;
        int tii = id[k]; id[k] = id[best]; id[best] = tii;
        tv[n * 3 + k] = v[k];
        ti[n * 3 + k] = id[k];
    }
}

// ---------------- final KL reduction --------------------------------------
__global__ void kl_kernel(const float* __restrict__ tv1, const float* __restrict__ m2k1,
                          const float* __restrict__ tv2, const float* __restrict__ m2k2,
                          float* __restrict__ out) {
    const int t = threadIdx.x;
    const float* a = (t < 256) ? (tv1 + t * 3) : (tv2 + (t - 256) * 3);
    const float* b = (t < 256) ? (m2k1 + t * 3) : (m2k2 + (t - 256) * 3);
    float x[3], y[3];
#pragma unroll
    for (int i = 0; i < 3; i++) { x[i] = a[i] / 3.0f; y[i] = b[i] / 3.0f; }
    float mx = fmaxf(x[0], fmaxf(x[1], x[2]));
    float my = fmaxf(y[0], fmaxf(y[1], y[2]));
    float sx = expf(x[0] - mx) + expf(x[1] - mx) + expf(x[2] - mx);
    float sy = expf(y[0] - my) + expf(y[1] - my) + expf(y[2] - my);
    float lsex = mx + logf(sx);
    float lsey = my + logf(sy);
    double local = 0.0;
#pragma unroll
    for (int i = 0; i < 3; i++) {
        float lp = x[i] - lsex;
        float lq = y[i] - lsey;
        local += (double)expf(lp) * (double)(lp - lq);
    }
    __shared__ double red[512];
    red[t] = local;
    __syncthreads();
    for (int off = 256; off > 0; off >>= 1) {
        if (t < off) red[t] += red[t + off];
        __syncthreads();
    }
    if (t == 0) out[0] = (float)red[0];
}

// ---------------- launcher -------------------------------------------------
extern "C" void kernel_launch(void* const* d_in, const int* in_sizes, int n_in,
                              void* d_out, int out_size) {
    const float* imgN_in = (const float*)d_in[0];
    const float* capN_in = (const float*)d_in[1];
    const float* imgP_in = (const float*)d_in[2];
    const float* capP_in = (const float*)d_in[3];
    float* out = (float*)d_out;

    float *imgN, *capN, *imgP, *capP, *pcm1, *pcm2, *tv1, *tv2, *m2k1, *m2k2, *sc8a, *sc8b;
    int *ti1, *ti2, *ti8a, *ti8b;
    uint8_t *imgNf, *capNf, *imgPf, *capPf;
    cudaGetSymbolAddress((void**)&imgN, g_imgN);
    cudaGetSymbolAddress((void**)&capN, g_capN);
    cudaGetSymbolAddress((void**)&imgP, g_imgP);
    cudaGetSymbolAddress((void**)&capP, g_capP);
    cudaGetSymbolAddress((void**)&imgNf, g_imgN_f8);
    cudaGetSymbolAddress((void**)&capNf, g_capN_f8);
    cudaGetSymbolAddress((void**)&imgPf, g_imgP_f8);
    cudaGetSymbolAddress((void**)&capPf, g_capP_f8);
    cudaGetSymbolAddress((void**)&pcm1, g_pcmax1);
    cudaGetSymbolAddress((void**)&pcm2, g_pcmax2);
    cudaGetSymbolAddress((void**)&ti8a, g_ti8a);
    cudaGetSymbolAddress((void**)&ti8b, g_ti8b);
    cudaGetSymbolAddress((void**)&sc8a, g_sc8a);
    cudaGetSymbolAddress((void**)&sc8b, g_sc8b);
    cudaGetSymbolAddress((void**)&tv1,  g_tv1);
    cudaGetSymbolAddress((void**)&ti1,  g_ti1);
    cudaGetSymbolAddress((void**)&tv2,  g_tv2);
    cudaGetSymbolAddress((void**)&ti2,  g_ti2);
    cudaGetSymbolAddress((void**)&m2k1, g_m2k1);
    cudaGetSymbolAddress((void**)&m2k2, g_m2k2);

    // Opt into >48KB dynamic smem (persistent attribute; skip inside capture).
    cudaStreamCaptureStatus st = cudaStreamCaptureStatusNone;
    cudaStreamIsCapturing(0, &st);
    if (st == cudaStreamCaptureStatusNone) {
        cudaFuncSetAttribute(gemm_colmax<36>, cudaFuncAttributeMaxDynamicSharedMemorySize, DYN_SMEM);
        cudaFuncSetAttribute(gemm_colmax<32>, cudaFuncAttributeMaxDynamicSharedMemorySize, DYN_SMEM);
    }

    // fused 4-tensor normalize (default stream)
    {
        int total_warps = 2 * ROWS_IMG + 2 * ROWS_CAP;
        norm4_kernel<<<(total_warps + 7) / 8, 256>>>(
            imgN_in, capN_in, imgP_in, capP_in,
            imgN, capN, imgP, capP,
            imgNf, capNf, imgPf, capPf);
    }

    // fork: stream s1 runs call 2 concurrently with call 1
    cudaEventRecord(g_si.e0, 0);
    cudaStreamWaitEvent(g_si.s1, g_si.e0, 0);

    // ---- call 1 (default stream): STL(img_n, img_p, cap_p) ----
    {
        dim3 grid(ROWS_IMG / TN, ROWS_IMG / TM);   // (72, 36)
        gemm_colmax<36><<<grid, 512, DYN_SMEM>>>(imgNf, imgPf, pcm1, ROWS_IMG);
        sim_topc_kernel<36, 36><<<Bn, 256>>>(pcm1, ROWS_IMG, ti8a);
        score3_kernel<36, 36, TOPC><<<Bn, TOPC * 36>>>(imgN, imgP, ti8a, sc8a);
        top3_ofc_kernel<<<Bn, 32>>>(sc8a, ti8a, tv1, ti1);
        score3_kernel<36, 32, 3><<<Bn, 3 * 32>>>(imgN, capP, ti1, m2k1);
    }
    // ---- call 2 (stream s1): STL(cap_n, cap_p, img_p) ----
    {
        dim3 grid(ROWS_CAP / TN, ROWS_CAP / TM);   // (64, 32)
        gemm_colmax<32><<<grid, 512, DYN_SMEM, g_si.s1>>>(capNf, capPf, pcm2, ROWS_CAP);
        sim_topc_kernel<32, 32><<<Bn, 256, 0, g_si.s1>>>(pcm2, ROWS_CAP, ti8b);
        score3_kernel<32, 32, TOPC><<<Bn, TOPC * 32, 0, g_si.s1>>>(capN, capP, ti8b, sc8b);
        top3_ofc_kernel<<<Bn, 32, 0, g_si.s1>>>(sc8b, ti8b, tv2, ti2);
        score3_kernel<32, 36, 3><<<Bn, 3 * 36, 0, g_si.s1>>>(capN, imgP, ti2, m2k2);
    }

    // join: default stream waits for call 2, then final KL
    cudaEventRecord(g_si.e2, g_si.s1);
    cudaStreamWaitEvent(0, g_si.e2, 0);
    kl_kernel<<<1, 512>>>(tv1, m2k1, tv2, m2k2, out);
}

// round 16
// speedup vs baseline: 1.2230x; 1.2230x over previous
#include <cuda_runtime.h>
#include <cuda_bf16.h>
#include <math.h>
#include <stdint.h>

#define DEV __device__ __forceinline__

constexpr int Bn   = 256;
constexpr int Rimg = 36;
constexpr int Lcap = 32;
constexpr int Dm   = 1024;
constexpr int ROWS_IMG = Bn * Rimg;   // 9216
constexpr int ROWS_CAP = Bn * Lcap;   // 8192
constexpr int TOPC = 8;               // candidates kept for exact rescoring

// ---- GEMM tiling: CTA 256x128, 512 threads, warp tile 64x32 ----
constexpr int TM = 256;
constexpr int TN = 128;
constexpr int KS = 32;                         // K per stage
constexpr int NSTG = Dm / KS;                  // 32 stages
constexpr int A_PL = TM * KS * 2;              // 16384 B
constexpr int B_PL = TN * KS * 2;              // 8192 B
constexpr int STG  = A_PL + B_PL;              // 24576 B per stage
constexpr int DYN_SMEM = 3 * STG + 1024;       // 74752 (3-stage ring + align)

// ---------------- device scratch (no allocations allowed) ----------------
__device__ float g_imgN[ROWS_IMG * Dm];
__device__ float g_capN[ROWS_CAP * Dm];
__device__ float g_imgP[ROWS_IMG * Dm];
__device__ float g_capP[ROWS_CAP * Dm];
__device__ __nv_bfloat16 g_imgN_hi[ROWS_IMG * Dm];
__device__ __nv_bfloat16 g_capN_hi[ROWS_CAP * Dm];
__device__ __nv_bfloat16 g_imgP_hi[ROWS_IMG * Dm];
__device__ __nv_bfloat16 g_capP_hi[ROWS_CAP * Dm];
__device__ float g_pcmax1[2 * Bn * ROWS_IMG];  // call-1 [slot][n][col]
__device__ float g_pcmax2[2 * Bn * ROWS_CAP];  // call-2 (streams overlap)
__device__ int   g_ti8a[Bn * TOPC];
__device__ int   g_ti8b[Bn * TOPC];
__device__ float g_cmx1[Bn * TOPC * 36];       // rescore colmax staging (call 1)
__device__ float g_cmx2[Bn * TOPC * 32];       // rescore colmax staging (call 2)
__device__ float g_tv1[Bn * 3];
__device__ int   g_ti1[Bn * 3];
__device__ float g_tv2[Bn * 3];
__device__ int   g_ti2[Bn * 3];
__device__ float g_m2k1[Bn * 3];
__device__ float g_m2k2[Bn * 3];

// ---- stream/event infra (host-side statics, created before any capture) --
namespace {
struct StreamInit {
    cudaStream_t s1;
    cudaEvent_t e0, e2;
    StreamInit() {
        cudaStreamCreateWithFlags(&s1, cudaStreamNonBlocking);
        cudaEventCreateWithFlags(&e0, cudaEventDisableTiming);
        cudaEventCreateWithFlags(&e2, cudaEventDisableTiming);
    }
};
StreamInit g_si;
}

// ---------------- PTX helpers ----------------
DEV unsigned smem_u32(const void* p) {
    unsigned a;
    asm("{ .reg .u64 t; cvta.to.shared.u64 t, %1; cvt.u32.u64 %0, t; }" : "=r"(a) : "l"(p));
    return a;
}
DEV void cp16u(unsigned smem_dst, const void* gmem_src) {
    asm volatile("cp.async.cg.shared.global [%0], [%1], 16;" :: "r"(smem_dst), "l"(gmem_src));
}
#define CP_COMMIT() asm volatile("cp.async.commit_group;")
#define CP_WAIT(n)  asm volatile("cp.async.wait_group %0;" :: "n"(n) : "memory")

DEV void ldsm4(unsigned* d, unsigned addr) {
    asm volatile("ldmatrix.sync.aligned.m8n8.x4.shared.b16 {%0,%1,%2,%3}, [%4];"
                 : "=r"(d[0]), "=r"(d[1]), "=r"(d[2]), "=r"(d[3]) : "r"(addr));
}
DEV void mma_bf16(float* c, const unsigned* a, unsigned b0, unsigned b1) {
    asm volatile(
        "mma.sync.aligned.m16n8k16.row.col.f32.bf16.bf16.f32 "
        "{%0,%1,%2,%3},{%4,%5,%6,%7},{%8,%9},{%0,%1,%2,%3};"
        : "+f"(c[0]), "+f"(c[1]), "+f"(c[2]), "+f"(c[3])
        : "r"(a[0]), "r"(a[1]), "r"(a[2]), "r"(a[3]), "r"(b0), "r"(b1));
}

// ---- fused L2-normalize of all four tensors; emit fp32 + bf16 -------------
__global__ void norm4_kernel(const float* __restrict__ i0, const float* __restrict__ i1,
                             const float* __restrict__ i2, const float* __restrict__ i3,
                             float* __restrict__ o0, float* __restrict__ o1,
                             float* __restrict__ o2, float* __restrict__ o3,
                             __nv_bfloat16* __restrict__ h0, __nv_bfloat16* __restrict__ h1,
                             __nv_bfloat16* __restrict__ h2, __nv_bfloat16* __restrict__ h3) {
    int gw = (blockIdx.x * blockDim.x + threadIdx.x) >> 5;
    int lane = threadIdx.x & 31;
    const float* in; float* out; __nv_bfloat16* oh; int row;
    if (gw < ROWS_IMG)                    { in = i0; out = o0; oh = h0; row = gw; }
    else if (gw < ROWS_IMG + ROWS_CAP)    { in = i1; out = o1; oh = h1; row = gw - ROWS_IMG; }
    else if (gw < 2 * ROWS_IMG + ROWS_CAP){ in = i2; out = o2; oh = h2; row = gw - ROWS_IMG - ROWS_CAP; }
    else if (gw < 2 * ROWS_IMG + 2 * ROWS_CAP)
                                          { in = i3; out = o3; oh = h3; row = gw - 2 * ROWS_IMG - ROWS_CAP; }
    else return;

    const float4* src = reinterpret_cast<const float4*>(in + (size_t)row * Dm);
    float4* dst       = reinterpret_cast<float4*>(out + (size_t)row * Dm);
    __nv_bfloat16* dh = oh + (size_t)row * Dm;
    float4 v[8];
    float ss = 0.f;
#pragma unroll
    for (int i = 0; i < 8; i++) {
        v[i] = src[lane + 32 * i];
        ss += v[i].x * v[i].x + v[i].y * v[i].y + v[i].z * v[i].z + v[i].w * v[i].w;
    }
#pragma unroll
    for (int o = 16; o > 0; o >>= 1) ss += __shfl_xor_sync(0xffffffffu, ss, o);
    float inv = 1.0f / fmaxf(sqrtf(ss), 1e-8f);
#pragma unroll
    for (int i = 0; i < 8; i++) {
        float4 w = v[i];
        w.x *= inv; w.y *= inv; w.z *= inv; w.w *= inv;
        dst[lane + 32 * i] = w;
        __nv_bfloat16 h4[4] = {
            __float2bfloat16_rn(w.x), __float2bfloat16_rn(w.y),
            __float2bfloat16_rn(w.z), __float2bfloat16_rn(w.w) };
        *(ushort4*)&dh[(lane + 32 * i) * 4] = *(ushort4*)h4;
    }
}

// ------- phase-1: 1-pass bf16 GEMM (round-6 config) + group colmax ---------
template <int R>
__global__ __launch_bounds__(512, 1)
void gemm_colmax(const __nv_bfloat16* __restrict__ Ahi,
                 const __nv_bfloat16* __restrict__ Bhi,
                 float* __restrict__ pcmax, int CT) {
    extern __shared__ char dynsm[];
    const int tid  = threadIdx.x;
    const int lane = tid & 31;
    const int wid  = tid >> 5;
    const int wm   = wid >> 2;        // 0..3 -> rows wm*64
    const int wn   = wid & 3;         // 0..3 -> cols wn*32

    const unsigned smb0 = smem_u32(dynsm);
    const unsigned smb  = (smb0 + 1023u) & ~1023u;
    char* smp = dynsm + (smb - smb0);

    const __nv_bfloat16* Ah = Ahi + (size_t)blockIdx.y * TM * Dm;
    const __nv_bfloat16* Bh = Bhi + (size_t)blockIdx.x * TN * Dm;

    float c[4][4][4];
#pragma unroll
    for (int mf = 0; mf < 4; mf++)
#pragma unroll
        for (int nf = 0; nf < 4; nf++)
#pragma unroll
            for (int r = 0; r < 4; r++) c[mf][nf][r] = 0.f;

    // ldmatrix lane address components (kk=0; kk=1 => XOR 32)
    const int rAl = lane & 15, hiA = lane >> 4;
    const unsigned offA = (unsigned)((wm * 64 + rAl) * 64 + ((hiA ^ ((rAl >> 1) & 3)) * 16));
    const int nB = ((lane >> 4) & 1) * 8 + (lane & 7), hiB = (lane >> 3) & 1;
    const unsigned offB = (unsigned)((wn * 32 + nB) * 64 + ((hiB ^ ((nB >> 1) & 3)) * 16));

    auto load_stage = [&](int s) {
        const unsigned sb = smb + (unsigned)(s % 3) * STG;
        const int k0 = s * KS;
#pragma unroll
        for (int i = 0; i < 3; i++) {
            int idx = tid + i * 512;              // 0..1535
            if (idx < 1024) {                     // A: 256 rows x 4 chunks
                int r = idx >> 2, ch = idx & 3;
                cp16u(sb + r * 64 + ((ch ^ ((r >> 1) & 3)) * 16),
                      Ah + (size_t)r * Dm + k0 + ch * 8);
            } else {                              // B: 128 rows x 4 chunks
                int t2 = idx - 1024;
                int r = t2 >> 2, ch = t2 & 3;
                cp16u(sb + A_PL + r * 64 + ((ch ^ ((r >> 1) & 3)) * 16),
                      Bh + (size_t)r * Dm + k0 + ch * 8);
            }
        }
        CP_COMMIT();
    };

    load_stage(0);
    load_stage(1);

#pragma unroll 1
    for (int s = 0; s < NSTG; s++) {
        if (s < NSTG - 1) { CP_WAIT(1); } else { CP_WAIT(0); }
        __syncthreads();

        const unsigned sb  = smb + (unsigned)(s % 3) * STG;
        const unsigned aAh = sb + offA;
        const unsigned aBh = sb + A_PL + offB;

#pragma unroll
        for (int kk = 0; kk < 2; kk++) {
            const unsigned kx = kk * 32;
            unsigned bh[2][4], af[4][4];
#pragma unroll
            for (int j = 0; j < 2; j++) ldsm4(bh[j], (aBh + j * 1024) ^ kx);
#pragma unroll
            for (int mf = 0; mf < 4; mf++) ldsm4(af[mf], (aAh + mf * 1024) ^ kx);
#pragma unroll
            for (int mf = 0; mf < 4; mf++)
#pragma unroll
                for (int j = 0; j < 2; j++)
#pragma unroll
                    for (int sub = 0; sub < 2; sub++) {
                        int nf = j * 2 + sub;
                        mma_bf16(c[mf][nf], af[mf], bh[j][sub * 2], bh[j][sub * 2 + 1]);
                    }
        }
        if (s + 2 < NSTG) load_stage(s + 2);
    }
    __syncthreads();

    // ---- epilogue: two 128-row halves through smem [128][132] -------------
    float* red = reinterpret_cast<float*>(smp);
    const int m0 = blockIdx.y * TM;
    const int col = tid;                   // only tid<128 scans
    const size_t colg = (size_t)blockIdx.x * TN + (col & 127);
    int   curg = m0 / R;
    float curv = -INFINITY;
    const int lr = lane >> 2;
    const int lc = (lane & 3) * 2;

#pragma unroll 1
    for (int h = 0; h < 2; h++) {
        if ((wm >> 1) == h) {
            const int r0 = (wm & 1) * 64;
#pragma unroll
            for (int mf = 0; mf < 4; mf++)
#pragma unroll
                for (int nf = 0; nf < 4; nf++) {
                    int rr = r0 + mf * 16 + lr;
                    int cc = wn * 32 + nf * 8 + lc;
                    *(float2*)&red[rr * 132 + cc]       = make_float2(c[mf][nf][0], c[mf][nf][1]);
                    *(float2*)&red[(rr + 8) * 132 + cc] = make_float2(c[mf][nf][2], c[mf][nf][3]);
                }
        }
        __syncthreads();
        if (tid < 128) {
#pragma unroll 1
            for (int r = 0; r < 128; r++) {
                int grp = (m0 + h * 128 + r) / R;
                float v = red[r * 132 + col];
                if (grp != curg) {
                    int slot = blockIdx.y - (curg * R) / TM;
                    pcmax[(size_t)slot * Bn * CT + (size_t)curg * CT + colg] = curv;
                    curg = grp;
                    curv = v;
                } else {
                    curv = fmaxf(curv, v);
                }
            }
        }
        __syncthreads();
    }
    if (tid < 128) {
        int slot = blockIdx.y - (curg * R) / TM;
        pcmax[(size_t)slot * Bn * CT + (size_t)curg * CT + colg] = curv;
    }
}

// ------- approximate sim row-sum + warp-select top-8 -----------------------
template <int L, int R>
__global__ void sim_top8_kernel(const float* __restrict__ pcmax, int CT,
                                int* __restrict__ ti8) {
    const int n = blockIdx.x;
    const int t = threadIdx.x;  // 256 candidate p's
    const bool two = ((n * R) / TM) != ((n * R + R - 1) / TM);
    const float* b0 = pcmax + (size_t)n * CT + (size_t)t * L;
    const float* b1 = b0 + (size_t)Bn * CT;
    float s = 0.f;
#pragma unroll
    for (int l = 0; l < L; l++) {
        float v = b0[l];
        if (two) v = fmaxf(v, b1[l]);
        s += v;
    }
    __shared__ float sv[256];
    sv[t] = s;
    __syncthreads();
    if (t < 32) {
        for (int k = 0; k < TOPC; k++) {
            float bv = -INFINITY; int bi = 0x7fffffff;
#pragma unroll
            for (int j = 0; j < 8; j++) {
                int e = t + 32 * j;
                float v = sv[e];
                if (v > bv || (v == bv && e < bi)) { bv = v; bi = e; }
            }
#pragma unroll
            for (int o = 16; o > 0; o >>= 1) {
                float ov = __shfl_xor_sync(0xffffffffu, bv, o);
                int oi = __shfl_xor_sync(0xffffffffu, bi, o);
                if (ov > bv || (ov == bv && oi < bi)) { bv = ov; bi = oi; }
            }
            if (t == 0) { ti8[n * TOPC + k] = bi; sv[bi] = -INFINITY; }
            __syncwarp();
        }
    }
}

// ---- L-split exact fp32 rescore: block = (n, half); writes colmax to gmem -
// thread = (cand, l within half). Inner loop identical to proven score3.
template <int R2, int L2, int CAND, int LS>
__global__ __launch_bounds__(CAND * LS)
void score3s_kernel(const float* __restrict__ A, const float* __restrict__ Bmat,
                    const int* __restrict__ ti, float* __restrict__ cmx) {
    constexpr int KC = 32;
    constexpr int THREADS = CAND * LS;
    __shared__ __align__(16) float As[R2][KC + 4];

    const int n = blockIdx.x >> 1;
    const int sp = blockIdx.x & 1;
    const int tid = threadIdx.x;
    const int cand = tid / LS;
    const int l = sp * LS + (tid % LS);
    const int p = ti[n * CAND + cand];

    const float* Ab = A + (size_t)n * R2 * Dm;
    const float* Bb = Bmat + ((size_t)p * L2 + l) * Dm;

    float acc[R2];
#pragma unroll
    for (int r = 0; r < R2; r++) acc[r] = 0.f;

#pragma unroll 1
    for (int c2 = 0; c2 < Dm / KC; c2++) {
        float4 b4[KC / 4];
#pragma unroll
        for (int q = 0; q < KC / 4; q++) b4[q] = *(const float4*)(Bb + c2 * KC + q * 4);
        __syncthreads();
        for (int idx = tid; idx < R2 * (KC / 4); idx += THREADS) {
            int r = idx / (KC / 4), q = idx % (KC / 4);
            *(float4*)&As[r][q * 4] = *(const float4*)(Ab + (size_t)r * Dm + c2 * KC + q * 4);
        }
        __syncthreads();
#pragma unroll
        for (int r = 0; r < R2; r++) {
#pragma unroll
            for (int q = 0; q < KC / 4; q++) {
                float4 a4 = *(const float4*)&As[r][q * 4];   // broadcast
                acc[r] = fmaf(a4.x, b4[q].x, acc[r]);
                acc[r] = fmaf(a4.y, b4[q].y, acc[r]);
                acc[r] = fmaf(a4.z, b4[q].z, acc[r]);
                acc[r] = fmaf(a4.w, b4[q].w, acc[r]);
            }
        }
    }

    float m = acc[0];
#pragma unroll
    for (int r = 1; r < R2; r++) m = fmaxf(m, acc[r]);
    cmx[((size_t)n * CAND + cand) * L2 + l] = m;
}

// ---- sum staged colmax over L; exact top-3 (low-idx tie-break) ------------
template <int L2>
__global__ void top3_sum_kernel(const float* __restrict__ cmx, const int* __restrict__ ti8,
                                float* __restrict__ tv, int* __restrict__ ti) {
    const int n = blockIdx.x;
    const int t = threadIdx.x;   // 32 threads
    __shared__ float sv[TOPC];
    if (t < TOPC) {
        const float* row = cmx + ((size_t)n * TOPC + t) * L2;
        float s = 0.f;
        for (int l = 0; l < L2; l++) s += row[l];
        sv[t] = s;
    }
    __syncwarp();
    if (t == 0) {
        float v[TOPC]; int id[TOPC];
#pragma unroll
        for (int j = 0; j < TOPC; j++) { v[j] = sv[j]; id[j] = ti8[n * TOPC + j]; }
        for (int k = 0; k < 3; k++) {
            int best = k;
            for (int j = k + 1; j < TOPC; j++)
                if (v[j] > v[best] || (v[j] == v[best] && id[j] < id[best])) best = j;
            float tvv = v[k]; v[k] = v[best]; v[best] = tvv;
            int tii = id[k]; id[k] = id[best]; id[best] = tii;
            tv[n * 3 + k] = v[k];
            ti[n * 3 + k] = id[k];
        }
    }
}

// ---- unsplit exact fp32 score (p2 path, proven R11 form) -----------------
template <int R2, int L2, int CAND>
__global__ __launch_bounds__(CAND * L2)
void score3_kernel(const float* __restrict__ A, const float* __restrict__ Bmat,
                   const int* __restrict__ ti, float* __restrict__ outv) {
    constexpr int KC = 32;
    constexpr int THREADS = CAND * L2;
    __shared__ __align__(16) float As[R2][KC + 4];
    __shared__ float cmax_sh[THREADS];

    const int n = blockIdx.x;
    const int tid = threadIdx.x;
    const int cand = tid / L2;
    const int l = tid % L2;
    const int p = ti[n * CAND + cand];

    const float* Ab = A + (size_t)n * R2 * Dm;
    const float* Bb = Bmat + ((size_t)p * L2 + l) * Dm;

    float acc[R2];
#pragma unroll
    for (int r = 0; r < R2; r++) acc[r] = 0.f;

#pragma unroll 1
    for (int c2 = 0; c2 < Dm / KC; c2++) {
        float4 b4[KC / 4];
#pragma unroll
        for (int q = 0; q < KC / 4; q++) b4[q] = *(const float4*)(Bb + c2 * KC + q * 4);
        __syncthreads();
        for (int idx = tid; idx < R2 * (KC / 4); idx += THREADS) {
            int r = idx / (KC / 4), q = idx % (KC / 4);
            *(float4*)&As[r][q * 4] = *(const float4*)(Ab + (size_t)r * Dm + c2 * KC + q * 4);
        }
        __syncthreads();
#pragma unroll
        for (int r = 0; r < R2; r++) {
#pragma unroll
            for (int q = 0; q < KC / 4; q++) {
                float4 a4 = *(const float4*)&As[r][q * 4];
                acc[r] = fmaf(a4.x, b4[q].x, acc[r]);
                acc[r] = fmaf(a4.y, b4[q].y, acc[r]);
                acc[r] = fmaf(a4.z, b4[q].z, acc[r]);
                acc[r] = fmaf(a4.w, b4[q].w, acc[r]);
            }
        }
    }

    float m = acc[0];
#pragma unroll
    for (int r = 1; r < R2; r++) m = fmaxf(m, acc[r]);
    cmax_sh[tid] = m;
    __syncthreads();
    if (tid < CAND) {
        float s = 0.f;
        for (int j = 0; j < L2; j++) s += cmax_sh[tid * L2 + j];
        outv[n * CAND + tid] = s;
    }
}

// ---------------- final KL reduction --------------------------------------
__global__ void kl_kernel(const float* __restrict__ tv1, const float* __restrict__ m2k1,
                          const float* __restrict__ tv2, const float* __restrict__ m2k2,
                          float* __restrict__ out) {
    const int t = threadIdx.x;
    const float* a = (t < 256) ? (tv1 + t * 3) : (tv2 + (t - 256) * 3);
    const float* b = (t < 256) ? (m2k1 + t * 3) : (m2k2 + (t - 256) * 3);
    float x[3], y[3];
#pragma unroll
    for (int i = 0; i < 3; i++) { x[i] = a[i] / 3.0f; y[i] = b[i] / 3.0f; }
    float mx = fmaxf(x[0], fmaxf(x[1], x[2]));
    float my = fmaxf(y[0], fmaxf(y[1], y[2]));
    float sx = expf(x[0] - mx) + expf(x[1] - mx) + expf(x[2] - mx);
    float sy = expf(y[0] - my) + expf(y[1] - my) + expf(y[2] - my);
    float lsex = mx + logf(sx);
    float lsey = my + logf(sy);
    double local = 0.0;
#pragma unroll
    for (int i = 0; i < 3; i++) {
        float lp = x[i] - lsex;
        float lq = y[i] - lsey;
        local += (double)expf(lp) * (double)(lp - lq);
    }
    __shared__ double red[512];
    red[t] = local;
    __syncthreads();
    for (int off = 256; off > 0; off >>= 1) {
        if (t < off) red[t] += red[t + off];
        __syncthreads();
    }
    if (t == 0) out[0] = (float)red[0];
}

// ---------------- launcher -------------------------------------------------
extern "C" void kernel_launch(void* const* d_in, const int* in_sizes, int n_in,
                              void* d_out, int out_size) {
    const float* imgN_in = (const float*)d_in[0];
    const float* capN_in = (const float*)d_in[1];
    const float* imgP_in = (const float*)d_in[2];
    const float* capP_in = (const float*)d_in[3];
    float* out = (float*)d_out;

    float *imgN, *capN, *imgP, *capP, *pcm1, *pcm2, *tv1, *tv2, *m2k1, *m2k2, *cmx1, *cmx2;
    int *ti1, *ti2, *ti8a, *ti8b;
    __nv_bfloat16 *imgNh, *capNh, *imgPh, *capPh;
    cudaGetSymbolAddress((void**)&imgN, g_imgN);
    cudaGetSymbolAddress((void**)&capN, g_capN);
    cudaGetSymbolAddress((void**)&imgP, g_imgP);
    cudaGetSymbolAddress((void**)&capP, g_capP);
    cudaGetSymbolAddress((void**)&imgNh, g_imgN_hi);
    cudaGetSymbolAddress((void**)&capNh, g_capN_hi);
    cudaGetSymbolAddress((void**)&imgPh, g_imgP_hi);
    cudaGetSymbolAddress((void**)&capPh, g_capP_hi);
    cudaGetSymbolAddress((void**)&pcm1, g_pcmax1);
    cudaGetSymbolAddress((void**)&pcm2, g_pcmax2);
    cudaGetSymbolAddress((void**)&ti8a, g_ti8a);
    cudaGetSymbolAddress((void**)&ti8b, g_ti8b);
    cudaGetSymbolAddress((void**)&cmx1, g_cmx1);
    cudaGetSymbolAddress((void**)&cmx2, g_cmx2);
    cudaGetSymbolAddress((void**)&tv1,  g_tv1);
    cudaGetSymbolAddress((void**)&ti1,  g_ti1);
    cudaGetSymbolAddress((void**)&tv2,  g_tv2);
    cudaGetSymbolAddress((void**)&ti2,  g_ti2);
    cudaGetSymbolAddress((void**)&m2k1, g_m2k1);
    cudaGetSymbolAddress((void**)&m2k2, g_m2k2);

    // Opt into >48KB dynamic smem (persistent attribute; skip inside capture).
    cudaStreamCaptureStatus st = cudaStreamCaptureStatusNone;
    cudaStreamIsCapturing(0, &st);
    if (st == cudaStreamCaptureStatusNone) {
        cudaFuncSetAttribute(gemm_colmax<36>, cudaFuncAttributeMaxDynamicSharedMemorySize, DYN_SMEM);
        cudaFuncSetAttribute(gemm_colmax<32>, cudaFuncAttributeMaxDynamicSharedMemorySize, DYN_SMEM);
    }

    // fused 4-tensor normalize (default stream)
    {
        int total_warps = 2 * ROWS_IMG + 2 * ROWS_CAP;
        norm4_kernel<<<(total_warps + 7) / 8, 256>>>(
            imgN_in, capN_in, imgP_in, capP_in,
            imgN, capN, imgP, capP,
            imgNh, capNh, imgPh, capPh);
    }

    // fork: stream s1 runs call 2 concurrently with call 1
    cudaEventRecord(g_si.e0, 0);
    cudaStreamWaitEvent(g_si.s1, g_si.e0, 0);

    // ---- call 1 (default stream): STL(img_n, img_p, cap_p) ----
    {
        dim3 grid(ROWS_IMG / TN, ROWS_IMG / TM);   // (72, 36)
        gemm_colmax<36><<<grid, 512, DYN_SMEM>>>(imgNh, imgPh, pcm1, ROWS_IMG);
        sim_top8_kernel<36, 36><<<Bn, 256>>>(pcm1, ROWS_IMG, ti8a);
        score3s_kernel<36, 36, TOPC, 18><<<Bn * 2, TOPC * 18>>>(imgN, imgP, ti8a, cmx1);
        top3_sum_kernel<36><<<Bn, 32>>>(cmx1, ti8a, tv1, ti1);
        score3_kernel<36, 32, 3><<<Bn, 3 * 32>>>(imgN, capP, ti1, m2k1);
    }
    // ---- call 2 (stream s1): STL(cap_n, cap_p, img_p) ----
    {
        dim3 grid(ROWS_CAP / TN, ROWS_CAP / TM);   // (64, 32)
        gemm_colmax<32><<<grid, 512, DYN_SMEM, g_si.s1>>>(capNh, capPh, pcm2, ROWS_CAP);
        sim_top8_kernel<32, 32><<<Bn, 256, 0, g_si.s1>>>(pcm2, ROWS_CAP, ti8b);
        score3s_kernel<32, 32, TOPC, 16><<<Bn * 2, TOPC * 16, 0, g_si.s1>>>(capN, capP, ti8b, cmx2);
        top3_sum_kernel<32><<<Bn, 32, 0, g_si.s1>>>(cmx2, ti8b, tv2, ti2);
        score3_kernel<32, 36, 3><<<Bn, 3 * 36, 0, g_si.s1>>>(capN, imgP, ti2, m2k2);
    }

    // join: default stream waits for call 2, then final KL
    cudaEventRecord(g_si.e2, g_si.s1);
    cudaStreamWaitEvent(0, g_si.e2, 0);
    kl_kernel<<<1, 512>>>(tv1, m2k1, tv2, m2k2, out);
}

// round 17
// speedup vs baseline: 1.3061x; 1.0679x over previous
#include <cuda_runtime.h>
#include <cuda_bf16.h>
#include <math.h>
#include <stdint.h>

#define DEV __device__ __forceinline__

constexpr int Bn   = 256;
constexpr int Rimg = 36;
constexpr int Lcap = 32;
constexpr int Dm   = 1024;
constexpr int ROWS_IMG = Bn * Rimg;   // 9216
constexpr int ROWS_CAP = Bn * Lcap;   // 8192
constexpr int TOPC = 6;               // candidates kept for exact rescoring

// ---- GEMM tiling: CTA 256x128, 512 threads, warp tile 64x32 ----
constexpr int TM = 256;
constexpr int TN = 128;
constexpr int KS = 32;                         // K per stage
constexpr int NSTG = Dm / KS;                  // 32 stages
constexpr int A_PL = TM * KS * 2;              // 16384 B
constexpr int B_PL = TN * KS * 2;              // 8192 B
constexpr int STG  = A_PL + B_PL;              // 24576 B per stage
constexpr int DYN_SMEM = 3 * STG + 1024;       // 74752 (3-stage ring + align)

// ---------------- device scratch (no allocations allowed) ----------------
__device__ float g_imgN[ROWS_IMG * Dm];
__device__ float g_capN[ROWS_CAP * Dm];
__device__ float g_imgP[ROWS_IMG * Dm];
__device__ float g_capP[ROWS_CAP * Dm];
__device__ __nv_bfloat16 g_imgN_hi[ROWS_IMG * Dm];
__device__ __nv_bfloat16 g_capN_hi[ROWS_CAP * Dm];
__device__ __nv_bfloat16 g_imgP_hi[ROWS_IMG * Dm];
__device__ __nv_bfloat16 g_capP_hi[ROWS_CAP * Dm];
__device__ float g_pcmax1[2 * Bn * ROWS_IMG];  // call-1 [slot][n][col]
__device__ float g_pcmax2[2 * Bn * ROWS_CAP];  // call-2 (streams overlap)
__device__ int   g_ti8a[Bn * TOPC];
__device__ int   g_ti8b[Bn * TOPC];
__device__ float g_sc8a[Bn * TOPC];
__device__ float g_sc8b[Bn * TOPC];
__device__ float g_tv1[Bn * 3];
__device__ int   g_ti1[Bn * 3];
__device__ float g_tv2[Bn * 3];
__device__ int   g_ti2[Bn * 3];
__device__ float g_m2k1[Bn * 3];
__device__ float g_m2k2[Bn * 3];

// ---- stream/event infra (host-side statics, created before any capture) --
namespace {
struct StreamInit {
    cudaStream_t s1;
    cudaEvent_t e0, e2;
    StreamInit() {
        cudaStreamCreateWithFlags(&s1, cudaStreamNonBlocking);
        cudaEventCreateWithFlags(&e0, cudaEventDisableTiming);
        cudaEventCreateWithFlags(&e2, cudaEventDisableTiming);
    }
};
StreamInit g_si;
}

// ---------------- PTX helpers ----------------
DEV unsigned smem_u32(const void* p) {
    unsigned a;
    asm("{ .reg .u64 t; cvta.to.shared.u64 t, %1; cvt.u32.u64 %0, t; }" : "=r"(a) : "l"(p));
    return a;
}
DEV void cp16u(unsigned smem_dst, const void* gmem_src) {
    asm volatile("cp.async.cg.shared.global [%0], [%1], 16;" :: "r"(smem_dst), "l"(gmem_src));
}
#define CP_COMMIT() asm volatile("cp.async.commit_group;")
#define CP_WAIT(n)  asm volatile("cp.async.wait_group %0;" :: "n"(n) : "memory")

DEV void ldsm4(unsigned* d, unsigned addr) {
    asm volatile("ldmatrix.sync.aligned.m8n8.x4.shared.b16 {%0,%1,%2,%3}, [%4];"
                 : "=r"(d[0]), "=r"(d[1]), "=r"(d[2]), "=r"(d[3]) : "r"(addr));
}
DEV void mma_bf16(float* c, const unsigned* a, unsigned b0, unsigned b1) {
    asm volatile(
        "mma.sync.aligned.m16n8k16.row.col.f32.bf16.bf16.f32 "
        "{%0,%1,%2,%3},{%4,%5,%6,%7},{%8,%9},{%0,%1,%2,%3};"
        : "+f"(c[0]), "+f"(c[1]), "+f"(c[2]), "+f"(c[3])
        : "r"(a[0]), "r"(a[1]), "r"(a[2]), "r"(a[3]), "r"(b0), "r"(b1));
}

// ---- fused L2-normalize of all four tensors; emit fp32 + bf16 -------------
__global__ void norm4_kernel(const float* __restrict__ i0, const float* __restrict__ i1,
                             const float* __restrict__ i2, const float* __restrict__ i3,
                             float* __restrict__ o0, float* __restrict__ o1,
                             float* __restrict__ o2, float* __restrict__ o3,
                             __nv_bfloat16* __restrict__ h0, __nv_bfloat16* __restrict__ h1,
                             __nv_bfloat16* __restrict__ h2, __nv_bfloat16* __restrict__ h3) {
    int gw = (blockIdx.x * blockDim.x + threadIdx.x) >> 5;
    int lane = threadIdx.x & 31;
    const float* in; float* out; __nv_bfloat16* oh; int row;
    if (gw < ROWS_IMG)                    { in = i0; out = o0; oh = h0; row = gw; }
    else if (gw < ROWS_IMG + ROWS_CAP)    { in = i1; out = o1; oh = h1; row = gw - ROWS_IMG; }
    else if (gw < 2 * ROWS_IMG + ROWS_CAP){ in = i2; out = o2; oh = h2; row = gw - ROWS_IMG - ROWS_CAP; }
    else if (gw < 2 * ROWS_IMG + 2 * ROWS_CAP)
                                          { in = i3; out = o3; oh = h3; row = gw - 2 * ROWS_IMG - ROWS_CAP; }
    else return;

    const float4* src = reinterpret_cast<const float4*>(in + (size_t)row * Dm);
    float4* dst       = reinterpret_cast<float4*>(out + (size_t)row * Dm);
    __nv_bfloat16* dh = oh + (size_t)row * Dm;
    float4 v[8];
    float ss = 0.f;
#pragma unroll
    for (int i = 0; i < 8; i++) {
        v[i] = src[lane + 32 * i];
        ss += v[i].x * v[i].x + v[i].y * v[i].y + v[i].z * v[i].z + v[i].w * v[i].w;
    }
#pragma unroll
    for (int o = 16; o > 0; o >>= 1) ss += __shfl_xor_sync(0xffffffffu, ss, o);
    float inv = 1.0f / fmaxf(sqrtf(ss), 1e-8f);
#pragma unroll
    for (int i = 0; i < 8; i++) {
        float4 w = v[i];
        w.x *= inv; w.y *= inv; w.z *= inv; w.w *= inv;
        dst[lane + 32 * i] = w;
        __nv_bfloat16 h4[4] = {
            __float2bfloat16_rn(w.x), __float2bfloat16_rn(w.y),
            __float2bfloat16_rn(w.z), __float2bfloat16_rn(w.w) };
        *(ushort4*)&dh[(lane + 32 * i) * 4] = *(ushort4*)h4;
    }
}

// ------- phase-1: 1-pass bf16 GEMM (round-6 config) + group colmax ---------
template <int R>
__global__ __launch_bounds__(512, 1)
void gemm_colmax(const __nv_bfloat16* __restrict__ Ahi,
                 const __nv_bfloat16* __restrict__ Bhi,
                 float* __restrict__ pcmax, int CT) {
    extern __shared__ char dynsm[];
    const int tid  = threadIdx.x;
    const int lane = tid & 31;
    const int wid  = tid >> 5;
    const int wm   = wid >> 2;        // 0..3 -> rows wm*64
    const int wn   = wid & 3;         // 0..3 -> cols wn*32

    const unsigned smb0 = smem_u32(dynsm);
    const unsigned smb  = (smb0 + 1023u) & ~1023u;
    char* smp = dynsm + (smb - smb0);

    const __nv_bfloat16* Ah = Ahi + (size_t)blockIdx.y * TM * Dm;
    const __nv_bfloat16* Bh = Bhi + (size_t)blockIdx.x * TN * Dm;

    float c[4][4][4];
#pragma unroll
    for (int mf = 0; mf < 4; mf++)
#pragma unroll
        for (int nf = 0; nf < 4; nf++)
#pragma unroll
            for (int r = 0; r < 4; r++) c[mf][nf][r] = 0.f;

    // ldmatrix lane address components (kk=0; kk=1 => XOR 32)
    const int rAl = lane & 15, hiA = lane >> 4;
    const unsigned offA = (unsigned)((wm * 64 + rAl) * 64 + ((hiA ^ ((rAl >> 1) & 3)) * 16));
    const int nB = ((lane >> 4) & 1) * 8 + (lane & 7), hiB = (lane >> 3) & 1;
    const unsigned offB = (unsigned)((wn * 32 + nB) * 64 + ((hiB ^ ((nB >> 1) & 3)) * 16));

    auto load_stage = [&](int s) {
        const unsigned sb = smb + (unsigned)(s % 3) * STG;
        const int k0 = s * KS;
#pragma unroll
        for (int i = 0; i < 3; i++) {
            int idx = tid + i * 512;              // 0..1535
            if (idx < 1024) {                     // A: 256 rows x 4 chunks
                int r = idx >> 2, ch = idx & 3;
                cp16u(sb + r * 64 + ((ch ^ ((r >> 1) & 3)) * 16),
                      Ah + (size_t)r * Dm + k0 + ch * 8);
            } else {                              // B: 128 rows x 4 chunks
                int t2 = idx - 1024;
                int r = t2 >> 2, ch = t2 & 3;
                cp16u(sb + A_PL + r * 64 + ((ch ^ ((r >> 1) & 3)) * 16),
                      Bh + (size_t)r * Dm + k0 + ch * 8);
            }
        }
        CP_COMMIT();
    };

    load_stage(0);
    load_stage(1);

#pragma unroll 1
    for (int s = 0; s < NSTG; s++) {
        if (s < NSTG - 1) { CP_WAIT(1); } else { CP_WAIT(0); }
        __syncthreads();

        const unsigned sb  = smb + (unsigned)(s % 3) * STG;
        const unsigned aAh = sb + offA;
        const unsigned aBh = sb + A_PL + offB;

#pragma unroll
        for (int kk = 0; kk < 2; kk++) {
            const unsigned kx = kk * 32;
            unsigned bh[2][4], af[4][4];
#pragma unroll
            for (int j = 0; j < 2; j++) ldsm4(bh[j], (aBh + j * 1024) ^ kx);
#pragma unroll
            for (int mf = 0; mf < 4; mf++) ldsm4(af[mf], (aAh + mf * 1024) ^ kx);
#pragma unroll
            for (int mf = 0; mf < 4; mf++)
#pragma unroll
                for (int j = 0; j < 2; j++)
#pragma unroll
                    for (int sub = 0; sub < 2; sub++) {
                        int nf = j * 2 + sub;
                        mma_bf16(c[mf][nf], af[mf], bh[j][sub * 2], bh[j][sub * 2 + 1]);
                    }
        }
        if (s + 2 < NSTG) load_stage(s + 2);
    }
    __syncthreads();

    // ---- epilogue: two 128-row halves through smem [128][132] -------------
    float* red = reinterpret_cast<float*>(smp);
    const int m0 = blockIdx.y * TM;
    const int col = tid;                   // only tid<128 scans
    const size_t colg = (size_t)blockIdx.x * TN + (col & 127);
    int   curg = m0 / R;
    float curv = -INFINITY;
    const int lr = lane >> 2;
    const int lc = (lane & 3) * 2;

#pragma unroll 1
    for (int h = 0; h < 2; h++) {
        if ((wm >> 1) == h) {
            const int r0 = (wm & 1) * 64;
#pragma unroll
            for (int mf = 0; mf < 4; mf++)
#pragma unroll
                for (int nf = 0; nf < 4; nf++) {
                    int rr = r0 + mf * 16 + lr;
                    int cc = wn * 32 + nf * 8 + lc;
                    *(float2*)&red[rr * 132 + cc]       = make_float2(c[mf][nf][0], c[mf][nf][1]);
                    *(float2*)&red[(rr + 8) * 132 + cc] = make_float2(c[mf][nf][2], c[mf][nf][3]);
                }
        }
        __syncthreads();
        if (tid < 128) {
#pragma unroll 1
            for (int r = 0; r < 128; r++) {
                int grp = (m0 + h * 128 + r) / R;
                float v = red[r * 132 + col];
                if (grp != curg) {
                    int slot = blockIdx.y - (curg * R) / TM;
                    pcmax[(size_t)slot * Bn * CT + (size_t)curg * CT + colg] = curv;
                    curg = grp;
                    curv = v;
                } else {
                    curv = fmaxf(curv, v);
                }
            }
        }
        __syncthreads();
    }
    if (tid < 128) {
        int slot = blockIdx.y - (curg * R) / TM;
        pcmax[(size_t)slot * Bn * CT + (size_t)curg * CT + colg] = curv;
    }
}

// ------- approximate sim row-sum + warp-select top-TOPC --------------------
template <int L, int R>
__global__ void sim_top8_kernel(const float* __restrict__ pcmax, int CT,
                                int* __restrict__ ti8) {
    const int n = blockIdx.x;
    const int t = threadIdx.x;  // 256 candidate p's
    const bool two = ((n * R) / TM) != ((n * R + R - 1) / TM);
    const float* b0 = pcmax + (size_t)n * CT + (size_t)t * L;
    const float* b1 = b0 + (size_t)Bn * CT;
    float s = 0.f;
#pragma unroll
    for (int l = 0; l < L; l++) {
        float v = b0[l];
        if (two) v = fmaxf(v, b1[l]);
        s += v;
    }
    __shared__ float sv[256];
    sv[t] = s;
    __syncthreads();
    // single warp does TOPC argmax rounds (low-index tie-break = jax top_k)
    if (t < 32) {
        for (int k = 0; k < TOPC; k++) {
            float bv = -INFINITY; int bi = 0x7fffffff;
#pragma unroll
            for (int j = 0; j < 8; j++) {
                int e = t + 32 * j;
                float v = sv[e];
                if (v > bv || (v == bv && e < bi)) { bv = v; bi = e; }
            }
#pragma unroll
            for (int o = 16; o > 0; o >>= 1) {
                float ov = __shfl_xor_sync(0xffffffffu, bv, o);
                int oi = __shfl_xor_sync(0xffffffffu, bi, o);
                if (ov > bv || (ov == bv && oi < bi)) { bv = ov; bi = oi; }
            }
            if (t == 0) { ti8[n * TOPC + k] = bi; sv[bi] = -INFINITY; }
            __syncwarp();
        }
    }
}

// ---- exact fp32 score (R11 proven form): A-tile shared across all --------
// candidates of one n. thread = (cand, l); float4 smem broadcast + FMA.
template <int R2, int L2, int CAND>
__global__ __launch_bounds__(CAND * L2)
void score3_kernel(const float* __restrict__ A, const float* __restrict__ Bmat,
                   const int* __restrict__ ti, float* __restrict__ outv) {
    constexpr int KC = 32;
    constexpr int THREADS = CAND * L2;
    __shared__ __align__(16) float As[R2][KC + 4];
    __shared__ float cmax_sh[THREADS];

    const int n = blockIdx.x;
    const int tid = threadIdx.x;
    const int cand = tid / L2;
    const int l = tid % L2;
    const int p = ti[n * CAND + cand];

    const float* Ab = A + (size_t)n * R2 * Dm;
    const float* Bb = Bmat + ((size_t)p * L2 + l) * Dm;

    float acc[R2];
#pragma unroll
    for (int r = 0; r < R2; r++) acc[r] = 0.f;

#pragma unroll 1
    for (int c2 = 0; c2 < Dm / KC; c2++) {
        float4 b4[KC / 4];
#pragma unroll
        for (int q = 0; q < KC / 4; q++) b4[q] = *(const float4*)(Bb + c2 * KC + q * 4);
        __syncthreads();
        for (int idx = tid; idx < R2 * (KC / 4); idx += THREADS) {
            int r = idx / (KC / 4), q = idx % (KC / 4);
            *(float4*)&As[r][q * 4] = *(const float4*)(Ab + (size_t)r * Dm + c2 * KC + q * 4);
        }
        __syncthreads();
#pragma unroll
        for (int r = 0; r < R2; r++) {
#pragma unroll
            for (int q = 0; q < KC / 4; q++) {
                float4 a4 = *(const float4*)&As[r][q * 4];   // broadcast
                acc[r] = fmaf(a4.x, b4[q].x, acc[r]);
                acc[r] = fmaf(a4.y, b4[q].y, acc[r]);
                acc[r] = fmaf(a4.z, b4[q].z, acc[r]);
                acc[r] = fmaf(a4.w, b4[q].w, acc[r]);
            }
        }
    }

    float m = acc[0];
#pragma unroll
    for (int r = 1; r < R2; r++) m = fmaxf(m, acc[r]);
    cmax_sh[tid] = m;
    __syncthreads();
    if (tid < CAND) {
        float s = 0.f;
        for (int j = 0; j < L2; j++) s += cmax_sh[tid * L2 + j];
        outv[n * CAND + tid] = s;
    }
}

// ---- exact top-3 of the TOPC rescored candidates (low-idx tie-break) ------
__global__ void top3_of8_kernel(const float* __restrict__ sc8, const int* __restrict__ ti8,
                                float* __restrict__ tv, int* __restrict__ ti) {
    const int n = blockIdx.x;
    if (threadIdx.x != 0) return;
    float v[TOPC]; int id[TOPC];
#pragma unroll
    for (int j = 0; j < TOPC; j++) { v[j] = sc8[n * TOPC + j]; id[j] = ti8[n * TOPC + j]; }
    for (int k = 0; k < 3; k++) {
        int best = k;
        for (int j = k + 1; j < TOPC; j++)
            if (v[j] > v[best] || (v[j] == v[best] && id[j] < id[best])) best = j;
        float tvv = v[k]; v[k] = v[best]; v[best] = tvv;
        int tii = id[k]; id[k] = id[best]; id[best] = tii;
        tv[n * 3 + k] = v[k];
        ti[n * 3 + k] = id[k];
    }
}

// ---------------- final KL reduction --------------------------------------
__global__ void kl_kernel(const float* __restrict__ tv1, const float* __restrict__ m2k1,
                          const float* __restrict__ tv2, const float* __restrict__ m2k2,
                          float* __restrict__ out) {
    const int t = threadIdx.x;
    const float* a = (t < 256) ? (tv1 + t * 3) : (tv2 + (t - 256) * 3);
    const float* b = (t < 256) ? (m2k1 + t * 3) : (m2k2 + (t - 256) * 3);
    float x[3], y[3];
#pragma unroll
    for (int i = 0; i < 3; i++) { x[i] = a[i] / 3.0f; y[i] = b[i] / 3.0f; }
    float mx = fmaxf(x[0], fmaxf(x[1], x[2]));
    float my = fmaxf(y[0], fmaxf(y[1], y[2]));
    float sx = expf(x[0] - mx) + expf(x[1] - mx) + expf(x[2] - mx);
    float sy = expf(y[0] - my) + expf(y[1] - my) + expf(y[2] - my);
    float lsex = mx + logf(sx);
    float lsey = my + logf(sy);
    double local = 0.0;
#pragma unroll
    for (int i = 0; i < 3; i++) {
        float lp = x[i] - lsex;
        float lq = y[i] - lsey;
        local += (double)expf(lp) * (double)(lp - lq);
    }
    __shared__ double red[512];
    red[t] = local;
    __syncthreads();
    for (int off = 256; off > 0; off >>= 1) {
        if (t < off) red[t] += red[t + off];
        __syncthreads();
    }
    if (t == 0) out[0] = (float)red[0];
}

// ---------------- launcher -------------------------------------------------
extern "C" void kernel_launch(void* const* d_in, const int* in_sizes, int n_in,
                              void* d_out, int out_size) {
    const float* imgN_in = (const float*)d_in[0];
    const float* capN_in = (const float*)d_in[1];
    const float* imgP_in = (const float*)d_in[2];
    const float* capP_in = (const float*)d_in[3];
    float* out = (float*)d_out;

    float *imgN, *capN, *imgP, *capP, *pcm1, *pcm2, *tv1, *tv2, *m2k1, *m2k2, *sc8a, *sc8b;
    int *ti1, *ti2, *ti8a, *ti8b;
    __nv_bfloat16 *imgNh, *capNh, *imgPh, *capPh;
    cudaGetSymbolAddress((void**)&imgN, g_imgN);
    cudaGetSymbolAddress((void**)&capN, g_capN);
    cudaGetSymbolAddress((void**)&imgP, g_imgP);
    cudaGetSymbolAddress((void**)&capP, g_capP);
    cudaGetSymbolAddress((void**)&imgNh, g_imgN_hi);
    cudaGetSymbolAddress((void**)&capNh, g_capN_hi);
    cudaGetSymbolAddress((void**)&imgPh, g_imgP_hi);
    cudaGetSymbolAddress((void**)&capPh, g_capP_hi);
    cudaGetSymbolAddress((void**)&pcm1, g_pcmax1);
    cudaGetSymbolAddress((void**)&pcm2, g_pcmax2);
    cudaGetSymbolAddress((void**)&ti8a, g_ti8a);
    cudaGetSymbolAddress((void**)&ti8b, g_ti8b);
    cudaGetSymbolAddress((void**)&sc8a, g_sc8a);
    cudaGetSymbolAddress((void**)&sc8b, g_sc8b);
    cudaGetSymbolAddress((void**)&tv1,  g_tv1);
    cudaGetSymbolAddress((void**)&ti1,  g_ti1);
    cudaGetSymbolAddress((void**)&tv2,  g_tv2);
    cudaGetSymbolAddress((void**)&ti2,  g_ti2);
    cudaGetSymbolAddress((void**)&m2k1, g_m2k1);
    cudaGetSymbolAddress((void**)&m2k2, g_m2k2);

    // Opt into >48KB dynamic smem (persistent attribute; skip inside capture).
    cudaStreamCaptureStatus st = cudaStreamCaptureStatusNone;
    cudaStreamIsCapturing(0, &st);
    if (st == cudaStreamCaptureStatusNone) {
        cudaFuncSetAttribute(gemm_colmax<36>, cudaFuncAttributeMaxDynamicSharedMemorySize, DYN_SMEM);
        cudaFuncSetAttribute(gemm_colmax<32>, cudaFuncAttributeMaxDynamicSharedMemorySize, DYN_SMEM);
    }

    // fused 4-tensor normalize (default stream)
    {
        int total_warps = 2 * ROWS_IMG + 2 * ROWS_CAP;
        norm4_kernel<<<(total_warps + 7) / 8, 256>>>(
            imgN_in, capN_in, imgP_in, capP_in,
            imgN, capN, imgP, capP,
            imgNh, capNh, imgPh, capPh);
    }

    // fork: stream s1 runs call 2 concurrently with call 1
    cudaEventRecord(g_si.e0, 0);
    cudaStreamWaitEvent(g_si.s1, g_si.e0, 0);

    // ---- call 1 (default stream): STL(img_n, img_p, cap_p) ----
    {
        dim3 grid(ROWS_IMG / TN, ROWS_IMG / TM);   // (72, 36)
        gemm_colmax<36><<<grid, 512, DYN_SMEM>>>(imgNh, imgPh, pcm1, ROWS_IMG);
        sim_top8_kernel<36, 36><<<Bn, 256>>>(pcm1, ROWS_IMG, ti8a);
        score3_kernel<36, 36, TOPC><<<Bn, TOPC * 36>>>(imgN, imgP, ti8a, sc8a);
        top3_of8_kernel<<<Bn, 32>>>(sc8a, ti8a, tv1, ti1);
        score3_kernel<36, 32, 3><<<Bn, 3 * 32>>>(imgN, capP, ti1, m2k1);
    }
    // ---- call 2 (stream s1): STL(cap_n, cap_p, img_p) ----
    {
        dim3 grid(ROWS_CAP / TN, ROWS_CAP / TM);   // (64, 32)
        gemm_colmax<32><<<grid, 512, DYN_SMEM, g_si.s1>>>(capNh, capPh, pcm2, ROWS_CAP);
        sim_top8_kernel<32, 32><<<Bn, 256, 0, g_si.s1>>>(pcm2, ROWS_CAP, ti8b);
        score3_kernel<32, 32, TOPC><<<Bn, TOPC * 32, 0, g_si.s1>>>(capN, capP, ti8b, sc8b);
        top3_of8_kernel<<<Bn, 32, 0, g_si.s1>>>(sc8b, ti8b, tv2, ti2);
        score3_kernel<32, 36, 3><<<Bn, 3 * 36, 0, g_si.s1>>>(capN, imgP, ti2, m2k2);
    }

    // join: default stream waits for call 2, then final KL
    cudaEventRecord(g_si.e2, g_si.s1);
    cudaStreamWaitEvent(0, g_si.e2, 0);
    kl_kernel<<<1, 512>>>(tv1, m2k1, tv2, m2k2, out);
}